// round 10
// baseline (speedup 1.0000x reference)
#include <cuda_runtime.h>
#include <cstddef>

#define Hd 10
#define Td 20
#define M1 5

using u64 = unsigned long long;

// ---- f32x2 packed helpers (sm_100+) ----
__device__ __forceinline__ u64 pack2(float lo, float hi) {
    u64 r; asm("mov.b64 %0, {%1, %2};" : "=l"(r) : "f"(lo), "f"(hi)); return r;
}
__device__ __forceinline__ void unpack2(u64 v, float &lo, float &hi) {
    asm("mov.b64 {%0, %1}, %2;" : "=f"(lo), "=f"(hi) : "l"(v));
}
__device__ __forceinline__ void fma2(u64 &d, u64 a, u64 b) {
    asm("fma.rn.f32x2 %0, %1, %2, %0;" : "+l"(d) : "l"(a), "l"(b));
}
__device__ __forceinline__ u64 fma2_3(u64 a, u64 b, u64 c) {
    u64 d; asm("fma.rn.f32x2 %0, %1, %2, %3;" : "=l"(d) : "l"(a), "l"(b), "l"(c)); return d;
}

// ---- activations ----
__device__ __forceinline__ float tanh_fast(float x) {
    float r; asm("tanh.approx.f32 %0, %1;" : "=f"(r) : "f"(x)); return r;
}
// sigmoid on a PRE-HALVED argument: sig(2y) where y = 0.5*x was accumulated
__device__ __forceinline__ float sigp(float y) {
    return fmaf(tanh_fast(y), 0.5f, 0.5f);          // MUFU + FFMA only
}
__device__ __forceinline__ float sig_acc(float x) {  // accurate, for final score
    return __fdividef(1.0f, 1.0f + __expf(-x));
}

__global__ void __launch_bounds__(256, 2)
lstm_disc_kernel(const float* __restrict__ values,
                 const float* __restrict__ masks,
                 const float* __restrict__ W_ih,   // (40,1)
                 const float* __restrict__ W_hh,   // (40,10) row-major
                 const float* __restrict__ b_ih,   // (40)
                 const float* __restrict__ b_hh,   // (40)
                 const float* __restrict__ W1,     // (5,10)
                 const float* __restrict__ b1,     // (5)
                 const float* __restrict__ W2,     // (1,5)
                 const float* __restrict__ b2,     // (1)
                 float* __restrict__ out,          // scores (B,T) then masks (B,T)
                 int B)
{
    // Lane-PAIR packed gate weights, i/f/o rows pre-scaled by 0.5 (exact).
    // Pairs pi: 0->(lanes 0,1) 1->(2,3) 2->(5,6) 3->(7,8); singles: lane 4 (q=0), lane 9 (q=1).
    // sWp[pi][k] = { 0.5Wi[u0],0.5Wi[u1], 0.5Wf[u0],0.5Wf[u1], Wg[u0],Wg[u1], 0.5Wo[u0],0.5Wo[u1] }
    __shared__ __align__(16) float sWp[4][Hd][8];   // 1280 B
    // sBXp[pi][0..7] = bias pairs (same order/scaling), [8..15] = W_ih pairs
    __shared__ __align__(16) float sBXp[4][16];
    __shared__ __align__(16) float sWs[2][Hd][4];   // single lanes {4,9}: {0.5i,0.5f,g,0.5o}
    __shared__ __align__(16) float sBXs[2][8];      // bias4 then wx4, scaled
    __shared__ __align__(16) float sW1r[M1][12];    // W1 rows (cols 10,11 unused)
    __shared__ float sB1[M1];
    __shared__ float sW2[M1];
    __shared__ float sB2;

    const int tid = threadIdx.x;
    // sWp
    for (int i = tid; i < 4 * Hd * 8; i += blockDim.x) {
        int pi = i / 80, r = i % 80, k = r / 8, s = r % 8;
        int g = s >> 1, d = s & 1;
        int u0 = 2 * pi + (pi >= 2 ? 1 : 0);
        float sc = (g == 2) ? 1.0f : 0.5f;
        sWp[pi][k][s] = sc * W_hh[(g * 10 + u0 + d) * Hd + k];
    }
    if (tid < 64) {
        int pi = tid / 16, r = tid % 16;
        int rr = (r < 8) ? r : r - 8;
        int g = rr >> 1, d = rr & 1;
        int u0 = 2 * pi + (pi >= 2 ? 1 : 0);
        int j = g * 10 + u0 + d;
        float sc = (g == 2) ? 1.0f : 0.5f;
        sBXp[pi][r] = (r < 8) ? sc * (b_ih[j] + b_hh[j]) : sc * W_ih[j];
    }
    if (tid < 2 * Hd * 4) {
        int si = tid / 40, r = tid % 40, k = r / 4, g = r % 4;
        int u = (si == 0) ? 4 : 9;
        float sc = (g == 2) ? 1.0f : 0.5f;
        sWs[si][k][g] = sc * W_hh[(g * 10 + u) * Hd + k];
    }
    if (tid < 16) {
        int si = tid / 8, r = tid % 8, g = r & 3;
        int u = (si == 0) ? 4 : 9;
        int j = g * 10 + u;
        float sc = (g == 2) ? 1.0f : 0.5f;
        sBXs[si][r] = (r < 4) ? sc * (b_ih[j] + b_hh[j]) : sc * W_ih[j];
    }
    if (tid < M1 * 12) {
        int j = tid / 12, k = tid % 12;
        sW1r[j][k] = (k < Hd) ? W1[j * Hd + k] : 0.0f;
    }
    if (tid < M1) { sB1[tid] = b1[tid]; sW2[tid] = W2[tid]; }
    if (tid == 0) sB2 = b2[0];
    __syncthreads();

    const int gtid = blockIdx.x * blockDim.x + tid;
    const int pr = gtid >> 1;            // pair of elements 2pr, 2pr+1
    const int q  = gtid & 1;             // lane-half: q=0 lanes 0-4, q=1 lanes 5-9
    const int nthreads = gridDim.x * blockDim.x;

    const int e0 = 2 * pr, e1 = 2 * pr + 1;
    if (e1 < B) {
        const float* __restrict__ vr0 = values + (size_t)e0 * Td;
        const float* __restrict__ vr1 = values + (size_t)e1 * Td;
        float* __restrict__ sr0 = out + (size_t)e0 * Td;
        float* __restrict__ sr1 = out + (size_t)e1 * Td;

        float h0[Hd], h1[Hd], c0[5], c1[5];
#pragma unroll
        for (int k = 0; k < Hd; k++) { h0[k] = 0.f; h1[k] = 0.f; }
#pragma unroll
        for (int k = 0; k < 5; k++) { c0[k] = 0.f; c1[k] = 0.f; }

#pragma unroll 1
        for (int t = 0; t < Td; t++) {
            // ---- MLP scoring head (pre-update h), rows split by parity ----
            float p0 = (q == 0) ? sB2 : 0.0f;
            float p1 = p0;
#pragma unroll
            for (int jj = 0; jj < 3; jj++) {
                const int j = 2 * jj + q;
                if (j < M1) {
                    const float4* __restrict__ wr = (const float4*)sW1r[j];
                    const float2 wt = *(const float2*)&sW1r[j][8];
                    float z0 = sB1[j], z1 = z0;
#pragma unroll
                    for (int p4 = 0; p4 < 2; p4++) {
                        const float4 w = wr[p4];
                        z0 = fmaf(h0[4 * p4],     w.x, z0);
                        z0 = fmaf(h0[4 * p4 + 1], w.y, z0);
                        z0 = fmaf(h0[4 * p4 + 2], w.z, z0);
                        z0 = fmaf(h0[4 * p4 + 3], w.w, z0);
                        z1 = fmaf(h1[4 * p4],     w.x, z1);
                        z1 = fmaf(h1[4 * p4 + 1], w.y, z1);
                        z1 = fmaf(h1[4 * p4 + 2], w.z, z1);
                        z1 = fmaf(h1[4 * p4 + 3], w.w, z1);
                    }
                    z0 = fmaf(h0[8], wt.x, z0); z0 = fmaf(h0[9], wt.y, z0);
                    z1 = fmaf(h1[8], wt.x, z1); z1 = fmaf(h1[9], wt.y, z1);
                    z0 = fmaxf(z0, 0.2f * z0);       // leaky_relu(0.2)
                    z1 = fmaxf(z1, 0.2f * z1);
                    const float w2j = sW2[j];
                    p0 = fmaf(w2j, z0, p0);
                    p1 = fmaf(w2j, z1, p1);
                }
            }
            const float op0 = __shfl_xor_sync(0xffffffffu, p0, 1);
            const float op1 = __shfl_xor_sync(0xffffffffu, p1, 1);
            if (q == 0) sr0[t] = sig_acc(p0 + op0);
            else        sr1[t] = sig_acc(p1 + op1);

            const float x0 = vr0[t];
            const float x1 = vr1[t];
            const u64 x0d = pack2(x0, x0);
            const u64 x1d = pack2(x1, x1);
            float hn0[5], hn1[5];

            // ---- lane-pair gates: 2 pairs via f32x2 ----
#pragma unroll
            for (int pp = 0; pp < 2; pp++) {
                const int pi = 2 * q + pp;
                const ulonglong2* __restrict__ bx = (const ulonglong2*)&sBXp[pi][0];
                const ulonglong2 bA = bx[0], bB = bx[1], wA = bx[2], wB = bx[3];
                u64 aI0 = fma2_3(x0d, wA.x, bA.x), aF0 = fma2_3(x0d, wA.y, bA.y);
                u64 aG0 = fma2_3(x0d, wB.x, bB.x), aO0 = fma2_3(x0d, wB.y, bB.y);
                u64 aI1 = fma2_3(x1d, wA.x, bA.x), aF1 = fma2_3(x1d, wA.y, bA.y);
                u64 aG1 = fma2_3(x1d, wB.x, bB.x), aO1 = fma2_3(x1d, wB.y, bB.y);

                const ulonglong2* __restrict__ wp = (const ulonglong2*)&sWp[pi][0][0];
#pragma unroll
                for (int k = 0; k < Hd; k++) {
                    const ulonglong2 wIF = wp[2 * k];      // (i-pair, f-pair)
                    const ulonglong2 wGO = wp[2 * k + 1];  // (g-pair, o-pair)
                    const u64 h0d = pack2(h0[k], h0[k]);
                    fma2(aI0, h0d, wIF.x); fma2(aF0, h0d, wIF.y);
                    fma2(aG0, h0d, wGO.x); fma2(aO0, h0d, wGO.y);
                    const u64 h1d = pack2(h1[k], h1[k]);
                    fma2(aI1, h1d, wIF.x); fma2(aF1, h1d, wIF.y);
                    fma2(aG1, h1d, wGO.x); fma2(aO1, h1d, wGO.y);
                }

                const int l = 2 * pp;        // local lane base
                float iA, iB, fA, fB, gA, gB, oA, oB;
                unpack2(aI0, iA, iB); unpack2(aF0, fA, fB);
                unpack2(aG0, gA, gB); unpack2(aO0, oA, oB);
                {
                    const float cnA = fmaf(sigp(fA), c0[l],     sigp(iA) * tanh_fast(gA));
                    const float cnB = fmaf(sigp(fB), c0[l + 1], sigp(iB) * tanh_fast(gB));
                    c0[l] = cnA; c0[l + 1] = cnB;
                    hn0[l]     = sigp(oA) * tanh_fast(cnA);
                    hn0[l + 1] = sigp(oB) * tanh_fast(cnB);
                }
                unpack2(aI1, iA, iB); unpack2(aF1, fA, fB);
                unpack2(aG1, gA, gB); unpack2(aO1, oA, oB);
                {
                    const float cnA = fmaf(sigp(fA), c1[l],     sigp(iA) * tanh_fast(gA));
                    const float cnB = fmaf(sigp(fB), c1[l + 1], sigp(iB) * tanh_fast(gB));
                    c1[l] = cnA; c1[l + 1] = cnB;
                    hn1[l]     = sigp(oA) * tanh_fast(cnA);
                    hn1[l + 1] = sigp(oB) * tanh_fast(cnB);
                }
            }

            // ---- single lane (local 4): scalar path ----
            {
                const float4 bi = *(const float4*)&sBXs[q][0];
                const float4 wx = *(const float4*)&sBXs[q][4];
                float aI0 = fmaf(x0, wx.x, bi.x), aF0 = fmaf(x0, wx.y, bi.y);
                float aG0 = fmaf(x0, wx.z, bi.z), aO0 = fmaf(x0, wx.w, bi.w);
                float aI1 = fmaf(x1, wx.x, bi.x), aF1 = fmaf(x1, wx.y, bi.y);
                float aG1 = fmaf(x1, wx.z, bi.z), aO1 = fmaf(x1, wx.w, bi.w);
                const float4* __restrict__ ws = (const float4*)&sWs[q][0][0];
#pragma unroll
                for (int k = 0; k < Hd; k++) {
                    const float4 w = ws[k];
                    const float a = h0[k], b = h1[k];
                    aI0 = fmaf(a, w.x, aI0);  aF0 = fmaf(a, w.y, aF0);
                    aG0 = fmaf(a, w.z, aG0);  aO0 = fmaf(a, w.w, aO0);
                    aI1 = fmaf(b, w.x, aI1);  aF1 = fmaf(b, w.y, aF1);
                    aG1 = fmaf(b, w.z, aG1);  aO1 = fmaf(b, w.w, aO1);
                }
                const float cn0 = fmaf(sigp(aF0), c0[4], sigp(aI0) * tanh_fast(aG0));
                const float cn1 = fmaf(sigp(aF1), c1[4], sigp(aI1) * tanh_fast(aG1));
                c0[4] = cn0; c1[4] = cn1;
                hn0[4] = sigp(aO0) * tanh_fast(cn0);
                hn1[4] = sigp(aO1) * tanh_fast(cn1);
            }

            // ---- exchange h halves with partner thread (both elements) ----
#pragma unroll
            for (int i = 0; i < 5; i++) {
                const float v0 = __shfl_xor_sync(0xffffffffu, hn0[i], 1);
                const float v1 = __shfl_xor_sync(0xffffffffu, hn1[i], 1);
                h0[i]     = (q == 0) ? hn0[i] : v0;
                h0[5 + i] = (q == 0) ? v0 : hn0[i];
                h1[i]     = (q == 0) ? hn1[i] : v1;
                h1[5 + i] = (q == 0) ? v1 : hn1[i];
            }
        }
    }

    // ---- masks passthrough: coalesced grid-stride float4 copy ----
    {
        const float4* __restrict__ mi = (const float4*)masks;
        float4* __restrict__ mo = (float4*)(out + (size_t)B * Td);
        const int n4 = (B * Td) / 4;
#pragma unroll 1
        for (int i = gtid; i < n4; i += nthreads) mo[i] = mi[i];
    }
}

extern "C" void kernel_launch(void* const* d_in, const int* in_sizes, int n_in,
                              void* d_out, int out_size)
{
    const float* values = (const float*)d_in[0];
    const float* masks  = (const float*)d_in[1];
    const float* W_ih   = (const float*)d_in[2];
    const float* W_hh   = (const float*)d_in[3];
    const float* b_ih   = (const float*)d_in[4];
    const float* b_hh   = (const float*)d_in[5];
    const float* W1     = (const float*)d_in[6];
    const float* b1     = (const float*)d_in[7];
    const float* W2     = (const float*)d_in[8];
    const float* b2     = (const float*)d_in[9];

    const int BT = in_sizes[0];          // B*T
    const int B  = BT / Td;
    float* out = (float*)d_out;

    const int nthreads = B;              // 2 threads per 2 elements
    lstm_disc_kernel<<<(nthreads + 255) / 256, 256>>>(
        values, masks, W_ih, W_hh, b_ih, b_hh, W1, b1, W2, b2, out, B);
}

// round 11
// speedup vs baseline: 1.1779x; 1.1779x over previous
#include <cuda_runtime.h>
#include <cstddef>

#define Hd 10
#define Td 20
#define M1 5

using u64 = unsigned long long;

// ---- f32x2 packed helpers (sm_100+) ----
__device__ __forceinline__ u64 pack2(float lo, float hi) {
    u64 r; asm("mov.b64 %0, {%1, %2};" : "=l"(r) : "f"(lo), "f"(hi)); return r;
}
__device__ __forceinline__ void unpack2(u64 v, float &lo, float &hi) {
    asm("mov.b64 {%0, %1}, %2;" : "=f"(lo), "=f"(hi) : "l"(v));
}
__device__ __forceinline__ void fma2(u64 &d, u64 a, u64 b) {
    asm("fma.rn.f32x2 %0, %1, %2, %0;" : "+l"(d) : "l"(a), "l"(b));
}
__device__ __forceinline__ u64 fma2_3(u64 a, u64 b, u64 c) {
    u64 d; asm("fma.rn.f32x2 %0, %1, %2, %3;" : "=l"(d) : "l"(a), "l"(b), "l"(c)); return d;
}

// ---- activations ----
__device__ __forceinline__ float tanh_fast(float x) {
    float r; asm("tanh.approx.f32 %0, %1;" : "=f"(r) : "f"(x)); return r;
}
// sigmoid of 2y, where y = 0.5*x was accumulated (0.5 folded into weights)
__device__ __forceinline__ float sigp(float y) {
    return fmaf(tanh_fast(y), 0.5f, 0.5f);          // MUFU + FFMA
}
__device__ __forceinline__ float sig_acc(float x) {  // accurate, for final score
    return __fdividef(1.0f, 1.0f + __expf(-x));
}

__global__ void __launch_bounds__(256, 2)
lstm_disc_kernel(const float* __restrict__ values,
                 const float* __restrict__ masks,
                 const float* __restrict__ W_ih,   // (40,1)
                 const float* __restrict__ W_hh,   // (40,10) row-major
                 const float* __restrict__ b_ih,   // (40)
                 const float* __restrict__ b_hh,   // (40)
                 const float* __restrict__ W1,     // (5,10)
                 const float* __restrict__ b1,     // (5)
                 const float* __restrict__ W2,     // (1,5)
                 const float* __restrict__ b2,     // (1)
                 float* __restrict__ out,          // scores (B,T) then masks (B,T)
                 int B)
{
    // Lane-major gate weights, i/f/o pre-scaled by 0.5 (exact binary scaling):
    // sW[u][k] = float4{ 0.5*Wi[u][k], 0.5*Wf[u][k], Wg[u][k], 0.5*Wo[u][k] }
    __shared__ __align__(16) float sW[Hd][Hd][4];   // 1600 B
    __shared__ __align__(16) float sBias[Hd][4];    // scaled biases, order {i,f,g,o}
    __shared__ __align__(16) float sWx[Hd][4];      // scaled W_ih, order {i,f,g,o}
    __shared__ __align__(16) float sW1r[M1][12];    // W1 rows padded to 12 (3x float4)
    __shared__ float sB1[M1];
    __shared__ float sW2[M1];
    __shared__ float sB2;

    const int tid = threadIdx.x;
    for (int i = tid; i < Hd * Hd * 4; i += blockDim.x) {
        int u = i / 40, r = i % 40, k = r / 4, g = r % 4;
        float sc = (g == 2) ? 1.0f : 0.5f;
        sW[u][k][g] = sc * W_hh[(g * 10 + u) * Hd + k];
    }
    if (tid < Hd * 4) {
        int u = tid / 4, g = tid % 4;
        int j = g * 10 + u;
        float sc = (g == 2) ? 1.0f : 0.5f;
        sBias[u][g] = sc * (b_ih[j] + b_hh[j]);
        sWx[u][g]   = sc * W_ih[j];
    }
    if (tid < M1 * 12) {
        int j = tid / 12, k = tid % 12;
        sW1r[j][k] = (k < Hd) ? W1[j * Hd + k] : 0.0f;
    }
    if (tid < M1) { sB1[tid] = b1[tid]; sW2[tid] = W2[tid]; }
    if (tid == 0) sB2 = b2[0];
    __syncthreads();

    const int gtid = blockIdx.x * blockDim.x + tid;
    const int pr = gtid >> 1;            // pair index -> elements 2pr, 2pr+1
    const int q  = gtid & 1;             // which lane-half this thread owns
    const int ub = 5 * q;
    const int nthreads = gridDim.x * blockDim.x;

    const int e0 = 2 * pr, e1 = 2 * pr + 1;
    if (e1 < B) {
        const float* __restrict__ vr0 = values + (size_t)e0 * Td;
        const float* __restrict__ vr1 = values + (size_t)e1 * Td;
        float* __restrict__ sr0 = out + (size_t)e0 * Td;
        float* __restrict__ sr1 = out + (size_t)e1 * Td;

        float h0[Hd + 2], h1[Hd + 2], c0[5], c1[5];
#pragma unroll
        for (int k = 0; k < Hd + 2; k++) { h0[k] = 0.f; h1[k] = 0.f; }
#pragma unroll
        for (int k = 0; k < 5; k++) { c0[k] = 0.f; c1[k] = 0.f; }

#pragma unroll 1
        for (int t = 0; t < Td; t++) {
            // ---- MLP scoring head (pre-update h), rows split by parity ----
            float p0 = (q == 0) ? sB2 : 0.0f;
            float p1 = p0;
#pragma unroll
            for (int jj = 0; jj < 3; jj++) {
                const int j = 2 * jj + q;
                if (j < M1) {
                    const float4* __restrict__ wr = (const float4*)sW1r[j];
                    float z0 = sB1[j], z1 = z0;
#pragma unroll
                    for (int p4 = 0; p4 < 3; p4++) {
                        const float4 w = wr[p4];
                        z0 = fmaf(h0[4 * p4],     w.x, z0);
                        z0 = fmaf(h0[4 * p4 + 1], w.y, z0);
                        z0 = fmaf(h0[4 * p4 + 2], w.z, z0);
                        z0 = fmaf(h0[4 * p4 + 3], w.w, z0);
                        z1 = fmaf(h1[4 * p4],     w.x, z1);
                        z1 = fmaf(h1[4 * p4 + 1], w.y, z1);
                        z1 = fmaf(h1[4 * p4 + 2], w.z, z1);
                        z1 = fmaf(h1[4 * p4 + 3], w.w, z1);
                    }
                    z0 = fmaxf(z0, 0.2f * z0);       // leaky_relu(0.2)
                    z1 = fmaxf(z1, 0.2f * z1);
                    const float w2j = sW2[j];
                    p0 = fmaf(w2j, z0, p0);
                    p1 = fmaf(w2j, z1, p1);
                }
            }
            const float op0 = __shfl_xor_sync(0xffffffffu, p0, 1);
            const float op1 = __shfl_xor_sync(0xffffffffu, p1, 1);
            if (q == 0) sr0[t] = sig_acc(p0 + op0);
            else        sr1[t] = sig_acc(p1 + op1);

            // ---- LSTM gates: R9 memory pattern, f32x2 accumulators (i,f)/(g,o) ----
            const float x0 = vr0[t];
            const float x1 = vr1[t];
            const u64 x0d = pack2(x0, x0);
            const u64 x1d = pack2(x1, x1);
            float hn0[5], hn1[5];
#pragma unroll
            for (int l = 0; l < 5; l++) {
                const int u = ub + l;
                const float4 bi = *(const float4*)sBias[u];
                const float4 wx = *(const float4*)sWx[u];
                const u64 biIF = pack2(bi.x, bi.y), biGO = pack2(bi.z, bi.w);
                const u64 wxIF = pack2(wx.x, wx.y), wxGO = pack2(wx.z, wx.w);
                u64 aIF0 = fma2_3(x0d, wxIF, biIF);
                u64 aGO0 = fma2_3(x0d, wxGO, biGO);
                u64 aIF1 = fma2_3(x1d, wxIF, biIF);
                u64 aGO1 = fma2_3(x1d, wxGO, biGO);

                const float4* __restrict__ wrow = (const float4*)&sW[u][0][0];
#pragma unroll
                for (int k = 0; k < Hd; k++) {
                    const float4 w = wrow[k];           // LDS.128 (same as R9)
                    const u64 wIF = pack2(w.x, w.y);
                    const u64 wGO = pack2(w.z, w.w);
                    const u64 h0d = pack2(h0[k], h0[k]);
                    fma2(aIF0, h0d, wIF);
                    fma2(aGO0, h0d, wGO);
                    const u64 h1d = pack2(h1[k], h1[k]);
                    fma2(aIF1, h1d, wIF);
                    fma2(aGO1, h1d, wGO);
                }

                float aI0, aF0, aG0, aO0, aI1, aF1, aG1, aO1;
                unpack2(aIF0, aI0, aF0); unpack2(aGO0, aG0, aO0);
                unpack2(aIF1, aI1, aF1); unpack2(aGO1, aG1, aO1);

                const float cn0 = fmaf(sigp(aF0), c0[l], sigp(aI0) * tanh_fast(aG0));
                const float cn1 = fmaf(sigp(aF1), c1[l], sigp(aI1) * tanh_fast(aG1));
                c0[l] = cn0; c1[l] = cn1;
                hn0[l] = sigp(aO0) * tanh_fast(cn0);
                hn1[l] = sigp(aO1) * tanh_fast(cn1);
            }

            // ---- exchange h halves with partner thread (both elements) ----
#pragma unroll
            for (int i = 0; i < 5; i++) {
                const float v0 = __shfl_xor_sync(0xffffffffu, hn0[i], 1);
                const float v1 = __shfl_xor_sync(0xffffffffu, hn1[i], 1);
                h0[i]     = (q == 0) ? hn0[i] : v0;
                h0[5 + i] = (q == 0) ? v0 : hn0[i];
                h1[i]     = (q == 0) ? hn1[i] : v1;
                h1[5 + i] = (q == 0) ? v1 : hn1[i];
            }
        }
    }

    // ---- masks passthrough: coalesced grid-stride float4 copy ----
    {
        const float4* __restrict__ mi = (const float4*)masks;
        float4* __restrict__ mo = (float4*)(out + (size_t)B * Td);
        const int n4 = (B * Td) / 4;
#pragma unroll 1
        for (int i = gtid; i < n4; i += nthreads) mo[i] = mi[i];
    }
}

extern "C" void kernel_launch(void* const* d_in, const int* in_sizes, int n_in,
                              void* d_out, int out_size)
{
    const float* values = (const float*)d_in[0];
    const float* masks  = (const float*)d_in[1];
    const float* W_ih   = (const float*)d_in[2];
    const float* W_hh   = (const float*)d_in[3];
    const float* b_ih   = (const float*)d_in[4];
    const float* b_hh   = (const float*)d_in[5];
    const float* W1     = (const float*)d_in[6];
    const float* b1     = (const float*)d_in[7];
    const float* W2     = (const float*)d_in[8];
    const float* b2     = (const float*)d_in[9];

    const int BT = in_sizes[0];          // B*T
    const int B  = BT / Td;
    float* out = (float*)d_out;

    const int nthreads = B;              // 2 threads per 2 elements
    lstm_disc_kernel<<<(nthreads + 255) / 256, 256>>>(
        values, masks, W_ih, W_hh, b_ih, b_hh, W1, b1, W2, b2, out, B);
}